// round 5
// baseline (speedup 1.0000x reference)
#include <cuda_runtime.h>
#include <cuda_fp16.h>
#include <mma.h>
#include <math.h>
using namespace nvcuda;

#define Sdim 1024
#define Bdim 8
#define Edim 512
#define Hdim 8
#define Ddim 64
#define Ndim 64   // B*H

// ---------------- scratch ----------------
__device__ float  g_q[(size_t)Ndim*Sdim*Ddim];        // [n][s][d] 16MB
__device__ float  g_k[(size_t)Ndim*Sdim*Ddim];
__device__ float  g_v[(size_t)Ndim*Sdim*Ddim];
__device__ float  g_bias[(size_t)Sdim*Sdim*Ndim];     // [j][i][n] 256MB
__device__ __half g_attn_h[(size_t)Ndim*Sdim*Sdim];   // [n][i][j] fp16 128MB
__device__ float  g_ctx[(size_t)Sdim*Bdim*Edim];      // [i][n*64+d] (= [m][e])
__device__ float  g_x[(size_t)Sdim*Bdim*Edim];

typedef wmma::fragment<wmma::matrix_a,16,16,8,wmma::precision::tf32,wmma::row_major> FragA;
typedef wmma::fragment<wmma::matrix_b,16,16,8,wmma::precision::tf32,wmma::col_major> FragBc;
typedef wmma::fragment<wmma::matrix_b,16,16,8,wmma::precision::tf32,wmma::row_major> FragBr;
typedef wmma::fragment<wmma::accumulator,16,16,8,float> FragC;

typedef wmma::fragment<wmma::matrix_a,16,16,16,__half,wmma::row_major> FragAh;
typedef wmma::fragment<wmma::matrix_b,16,16,16,__half,wmma::row_major> FragBh;
typedef wmma::fragment<wmma::accumulator,16,16,16,float> FragCh;

template<class F> __device__ __forceinline__ void cvt_tf32(F& f){
    #pragma unroll
    for(int i=0;i<f.num_elements;i++) f.x[i]=wmma::__float_to_tf32(f.x[i]);
}

// =======================================================================
// K1: QKV projection (tf32 TC).
// =======================================================================
__global__ void __launch_bounds__(256) proj_tc(const float* __restrict__ X,
    const float* __restrict__ W, const float* __restrict__ bias, int sel)
{
    __shared__ float sx[128*72];
    int tid=threadIdx.x, w=tid>>5;
    int m0=blockIdx.x*128, o0=blockIdx.y*64;
    int wy=w&3, wx=w>>2;
    FragC acc[2][2];
    #pragma unroll
    for(int r=0;r<2;r++)
        #pragma unroll
        for(int c=0;c<2;c++) wmma::fill_fragment(acc[r][c],0.f);

    for(int k0=0;k0<Edim;k0+=8){
        FragA a[2]; FragBc b[2];
        #pragma unroll
        for(int r=0;r<2;r++){
            wmma::load_matrix_sync(a[r], X+(size_t)(m0+wy*32+r*16)*Edim+k0, Edim);
            cvt_tf32(a[r]);
        }
        #pragma unroll
        for(int c=0;c<2;c++){
            wmma::load_matrix_sync(b[c], W+(size_t)(o0+wx*32+c*16)*Edim+k0, Edim);
            cvt_tf32(b[c]);
        }
        #pragma unroll
        for(int r=0;r<2;r++)
            #pragma unroll
            for(int c=0;c<2;c++) wmma::mma_sync(acc[r][c],a[r],b[c],acc[r][c]);
    }
    #pragma unroll
    for(int r=0;r<2;r++)
        #pragma unroll
        for(int c=0;c<2;c++)
            wmma::store_matrix_sync(&sx[(wy*32+r*16)*72+wx*32+c*16],acc[r][c],72,wmma::mem_row_major);
    __syncthreads();

    float* out=(sel==0)?g_q:((sel==1)?g_k:g_v);
    int r=tid>>1, half=tid&1;
    int m=m0+r, s=m>>3, bb=m&7, h=blockIdx.y;
    size_t base=((size_t)(bb*Hdim+h)*Sdim+s)*Ddim + half*32;
    #pragma unroll
    for(int u=0;u<8;u++){
        int d=half*32+u*4;
        float4 v=*(float4*)&sx[r*72+d];
        v.x+=bias[o0+d]; v.y+=bias[o0+d+1]; v.z+=bias[o0+d+2]; v.w+=bias[o0+d+3];
        *(float4*)&out[base+u*4]=v;
    }
}

// =======================================================================
// K2: edge-key bias (tf32 TC).  per j: bias[j][i][n] = ek[j][i][:] . q[n][j][:]
// =======================================================================
__global__ void __launch_bounds__(256) biasgemm_tc(const float* __restrict__ ek)
{
    __shared__ float Bs[64*72];     // [n][d], pre-converted tf32
    int tid=threadIdx.x, w=tid>>5;
    int i0=blockIdx.x*128; int j=blockIdx.y;

    for(int idx=tid; idx<4096; idx+=256){
        int n=idx>>6, d=idx&63;
        Bs[n*72+d]=wmma::__float_to_tf32(g_q[(size_t)n*(Sdim*Ddim)+(size_t)j*Ddim+d]);
    }
    __syncthreads();

    FragC acc[4];
    #pragma unroll
    for(int c=0;c<4;c++) wmma::fill_fragment(acc[c],0.f);
    const float* ekp = ek + (size_t)j*(Sdim*Ddim) + (size_t)(i0+w*16)*Ddim;
    #pragma unroll
    for(int kk=0;kk<8;kk++){
        FragA a;
        wmma::load_matrix_sync(a, ekp+kk*8, Ddim); cvt_tf32(a);
        #pragma unroll
        for(int c=0;c<4;c++){
            FragBc b;
            wmma::load_matrix_sync(b, &Bs[(c*16)*72+kk*8], 72);
            wmma::mma_sync(acc[c],a,b,acc[c]);
        }
    }
    #pragma unroll
    for(int c=0;c<4;c++)
        wmma::store_matrix_sync(&g_bias[(size_t)j*(Sdim*Ndim)+(size_t)(i0+w*16)*Ndim+c*16],
                                acc[c], Ndim, wmma::mem_row_major);
}

// =======================================================================
// K3: FUSED attention: QK^T + bias + mask + softmax + PV for one (n, 32-row i-tile)
// dynamic smem: probs[32][1032] fp32 (132KB)
// =======================================================================
extern __shared__ float s_probs[];
__global__ void __launch_bounds__(256) fused_attn(const int* __restrict__ mask)
{
    const int LDP = 1032;
    int tid=threadIdx.x, w=tid>>5, lane=tid&31;
    int n  = blockIdx.x;        // n fastest -> same-i-tile blocks co-resident
    int i0 = blockIdx.y*32;
    int wy = w&1, wx = w>>1;    // 2 i-strips x 4 j/d-strips

    // ---- pass 1: raw QK^T into smem probs ----
    FragA aq[8];
    {
        const float* qp = g_q + (size_t)n*(Sdim*Ddim) + (size_t)(i0+wy*16)*Ddim;
        #pragma unroll
        for(int kk=0;kk<8;kk++){ wmma::load_matrix_sync(aq[kk], qp+kk*8, Ddim); cvt_tf32(aq[kk]); }
    }
    for(int j0=0;j0<Sdim;j0+=64){
        FragC acc; wmma::fill_fragment(acc,0.f);
        const float* kp = g_k + (size_t)n*(Sdim*Ddim) + (size_t)(j0+wx*16)*Ddim;
        #pragma unroll
        for(int kk=0;kk<8;kk++){
            FragBc b; wmma::load_matrix_sync(b, kp+kk*8, Ddim); cvt_tf32(b);
            wmma::mma_sync(acc,aq[kk],b,acc);
        }
        wmma::store_matrix_sync(&s_probs[(wy*16)*LDP + j0 + wx*16], acc, LDP, wmma::mem_row_major);
    }
    __syncthreads();

    // ---- pass 2: bias + scale + mask + softmax, write fp16 probs ----
    #pragma unroll
    for(int rr=0; rr<4; rr++){
        int row = w*4+rr, gi = i0+row;
        const int* mrow = mask + ((size_t)n*Sdim + gi)*Sdim;
        float x[32];
        float mx = -1e30f;
        #pragma unroll
        for(int t=0;t<32;t++){
            int j = t*32 + lane;
            float qk = s_probs[row*LDP + j];
            float bs = g_bias[(size_t)j*(Sdim*Ndim) + (size_t)gi*Ndim + n];
            float v = mrow[j] ? -1e30f : (qk+bs)*0.125f;
            x[t]=v; mx=fmaxf(mx,v);
        }
        #pragma unroll
        for(int o=16;o;o>>=1) mx=fmaxf(mx,__shfl_xor_sync(0xffffffffu,mx,o));
        float sm=0.f;
        #pragma unroll
        for(int t=0;t<32;t++){ x[t]=__expf(x[t]-mx); sm+=x[t]; }
        #pragma unroll
        for(int o=16;o;o>>=1) sm+=__shfl_xor_sync(0xffffffffu,sm,o);
        float inv = 1.0f/sm;
        __half* arow = g_attn_h + (size_t)n*(Sdim*Sdim) + (size_t)gi*Sdim;
        #pragma unroll
        for(int t=0;t<32;t++){
            int j = t*32 + lane;
            float p = x[t]*inv;
            s_probs[row*LDP + j] = p;
            arow[j] = __float2half(p);
        }
    }
    __syncthreads();

    // ---- pass 3: PV -> g_ctx[i][n*64+d] ----
    FragC o; wmma::fill_fragment(o,0.f);
    const float* vp = g_v + (size_t)n*(Sdim*Ddim) + wx*16;
    for(int j0=0;j0<Sdim;j0+=8){
        FragA a; wmma::load_matrix_sync(a, &s_probs[(wy*16)*LDP + j0], LDP); cvt_tf32(a);
        FragBr b; wmma::load_matrix_sync(b, vp + (size_t)j0*Ddim, Ddim); cvt_tf32(b);
        wmma::mma_sync(o,a,b,o);
    }
    wmma::store_matrix_sync(&g_ctx[(size_t)(i0+wy*16)*(Bdim*Edim) + (size_t)n*Ddim + wx*16],
                            o, Bdim*Edim, wmma::mem_row_major);
}

// =======================================================================
// K4: edge-value (fp16 TC).  per i: ctx[i][n*64+d] += attn[:,i,:] @ ev[i]
// 8 warps: 4 n-strips x 2 d-halves (each d-half = 2 frags of 16)
// =======================================================================
__global__ void __launch_bounds__(256) ev_tc(const float* __restrict__ ev)
{
    __shared__ __half es[64*72];
    int tid=threadIdx.x, w=tid>>5;
    int wn=w&3, wd=w>>2;
    int i=blockIdx.x;
    FragCh acc[2];
    #pragma unroll
    for(int c=0;c<2;c++)
        wmma::load_matrix_sync(acc[c],
            &g_ctx[(size_t)i*(Bdim*Edim) + (size_t)(wn*16)*Ddim + wd*32 + c*16],
            Ddim, wmma::mem_row_major);

    const __half* ap_base = g_attn_h + (size_t)(wn*16)*(Sdim*Sdim) + (size_t)i*Sdim;
    for(int j0=0;j0<Sdim;j0+=64){
        for(int idx=tid; idx<4096; idx+=256){
            int jj=idx>>6, d=idx&63;
            es[jj*72+d]=__float2half(ev[(size_t)i*(Sdim*Ddim)+(size_t)(j0+jj)*Ddim+d]);
        }
        __syncthreads();
        #pragma unroll
        for(int kk=0;kk<4;kk++){
            FragAh a;
            wmma::load_matrix_sync(a, ap_base + j0 + kk*16, Sdim*Sdim);
            #pragma unroll
            for(int c=0;c<2;c++){
                FragBh b;
                wmma::load_matrix_sync(b, &es[(kk*16)*72 + wd*32 + c*16], 72);
                wmma::mma_sync(acc[c],a,b,acc[c]);
            }
        }
        __syncthreads();
    }
    #pragma unroll
    for(int c=0;c<2;c++)
        wmma::store_matrix_sync(&g_ctx[(size_t)i*(Bdim*Edim) + (size_t)(wn*16)*Ddim + wd*32 + c*16],
                                acc[c], Ddim, wmma::mem_row_major);
}

// =======================================================================
// K5: output projection + residual (tf32 TC) -> g_x
// =======================================================================
__global__ void __launch_bounds__(256) outproj_tc(const float* __restrict__ W,
    const float* __restrict__ bias, const float* __restrict__ resid)
{
    __shared__ float sx[128*72];
    int tid=threadIdx.x, w=tid>>5;
    int m0=blockIdx.x*128, o0=blockIdx.y*64;
    int wy=w&3, wx=w>>2;
    FragC acc[2][2];
    #pragma unroll
    for(int r=0;r<2;r++)
        #pragma unroll
        for(int c=0;c<2;c++) wmma::fill_fragment(acc[r][c],0.f);

    for(int k0=0;k0<Edim;k0+=8){
        FragA a[2]; FragBc b[2];
        #pragma unroll
        for(int r=0;r<2;r++){
            wmma::load_matrix_sync(a[r], g_ctx+(size_t)(m0+wy*32+r*16)*Edim+k0, Edim);
            cvt_tf32(a[r]);
        }
        #pragma unroll
        for(int c=0;c<2;c++){
            wmma::load_matrix_sync(b[c], W+(size_t)(o0+wx*32+c*16)*Edim+k0, Edim);
            cvt_tf32(b[c]);
        }
        #pragma unroll
        for(int r=0;r<2;r++)
            #pragma unroll
            for(int c=0;c<2;c++) wmma::mma_sync(acc[r][c],a[r],b[c],acc[r][c]);
    }
    #pragma unroll
    for(int r=0;r<2;r++)
        #pragma unroll
        for(int c=0;c<2;c++)
            wmma::store_matrix_sync(&sx[(wy*32+r*16)*72+wx*32+c*16],acc[r][c],72,wmma::mem_row_major);
    __syncthreads();

    int r=tid>>1, half=tid&1;
    int m=m0+r;
    size_t base=(size_t)m*Edim + o0 + half*32;
    #pragma unroll
    for(int u=0;u<8;u++){
        int d=half*32+u*4;
        float4 v=*(float4*)&sx[r*72+d];
        float4 rs=*(const float4*)&resid[base+u*4];
        v.x+=bias[o0+d]  +rs.x; v.y+=bias[o0+d+1]+rs.y;
        v.z+=bias[o0+d+2]+rs.z; v.w+=bias[o0+d+3]+rs.w;
        *(float4*)&g_x[base+u*4]=v;
    }
}

// =======================================================================
// K6: LayerNorm over last dim (512)
// =======================================================================
__global__ void __launch_bounds__(256) ln_kernel(const float* __restrict__ gamma,
     const float* __restrict__ beta, float* __restrict__ out)
{
    int m = blockIdx.x, tid = threadIdx.x;
    float a = g_x[(size_t)m*Edim + tid];
    float b = g_x[(size_t)m*Edim + 256 + tid];
    __shared__ float s1[256], s2[256];
    s1[tid] = a+b; s2[tid] = a*a + b*b;
    __syncthreads();
    for (int s=128;s>0;s>>=1){
        if(tid<s){ s1[tid]+=s1[tid+s]; s2[tid]+=s2[tid+s]; }
        __syncthreads();
    }
    float mean = s1[0] * (1.0f/512.0f);
    float var  = s2[0] * (1.0f/512.0f) - mean*mean;
    float rstd = rsqrtf(var + 1e-5f);
    out[(size_t)m*Edim + tid]       = gamma[tid]*(a-mean)*rstd + beta[tid];
    out[(size_t)m*Edim + 256 + tid] = gamma[256+tid]*(b-mean)*rstd + beta[256+tid];
}

// =======================================================================
extern "C" void kernel_launch(void* const* d_in, const int* in_sizes, int n_in,
                              void* d_out, int out_size)
{
    const float* query      = (const float*)d_in[0];
    const float* key        = (const float*)d_in[1];
    const float* value      = (const float*)d_in[2];
    const float* edge_key   = (const float*)d_in[3];
    const float* edge_value = (const float*)d_in[4];
    const int*   mask       = (const int*)  d_in[5];
    int base = (n_in == 17) ? 7 : 6;
    const float* Wq = (const float*)d_in[base+0];
    const float* bq = (const float*)d_in[base+1];
    const float* Wk = (const float*)d_in[base+2];
    const float* bk = (const float*)d_in[base+3];
    const float* Wv = (const float*)d_in[base+4];
    const float* bv = (const float*)d_in[base+5];
    const float* Wo = (const float*)d_in[base+6];
    const float* bo = (const float*)d_in[base+7];
    const float* gamma = (const float*)d_in[base+8];
    const float* beta  = (const float*)d_in[base+9];

    const int PROBS_SMEM = 32*1032*4;   // 132 KB
    cudaFuncSetAttribute(fused_attn, cudaFuncAttributeMaxDynamicSharedMemorySize, PROBS_SMEM);

    proj_tc<<<dim3(64,8),256>>>(query, Wq, bq, 0);
    proj_tc<<<dim3(64,8),256>>>(key,   Wk, bk, 1);
    proj_tc<<<dim3(64,8),256>>>(value, Wv, bv, 2);
    biasgemm_tc<<<dim3(8,1024),256>>>(edge_key);
    fused_attn<<<dim3(64,32),256,PROBS_SMEM>>>(mask);
    ev_tc<<<1024,256>>>(edge_value);
    outproj_tc<<<dim3(64,8),256>>>(Wo, bo, query);
    ln_kernel<<<dim3(8192),256>>>(gamma, beta, (float*)d_out);
}

// round 6
// speedup vs baseline: 1.6773x; 1.6773x over previous
#include <cuda_runtime.h>
#include <cuda_fp16.h>
#include <mma.h>
#include <math.h>
using namespace nvcuda;

#define Sdim 1024
#define Bdim 8
#define Edim 512
#define Hdim 8
#define Ddim 64
#define Ndim 64   // B*H

// ---------------- scratch ----------------
__device__ float  g_q[(size_t)Ndim*Sdim*Ddim];         // [n][s][d] 16MB
__device__ float  g_k[(size_t)Ndim*Sdim*Ddim];
__device__ float  g_v[(size_t)Ndim*Sdim*Ddim];
__device__ __half g_bias_h[(size_t)Sdim*Sdim*Ndim];    // [j][i][n] fp16 128MB
__device__ float  g_attn[(size_t)Ndim*Sdim*Sdim];      // logits fp32 [n][i][j] 256MB
__device__ __half g_attn_h[(size_t)Ndim*Sdim*Sdim];    // probs fp16 128MB
__device__ float  g_ctx[(size_t)Sdim*Bdim*Edim];       // [i][n*64+d]
__device__ float  g_x[(size_t)Sdim*Bdim*Edim];

typedef wmma::fragment<wmma::matrix_a,16,16,8,wmma::precision::tf32,wmma::row_major> FragA;
typedef wmma::fragment<wmma::matrix_b,16,16,8,wmma::precision::tf32,wmma::col_major> FragBc;
typedef wmma::fragment<wmma::accumulator,16,16,8,float> FragC;
typedef wmma::fragment<wmma::matrix_a,16,16,16,__half,wmma::row_major> FragAh;
typedef wmma::fragment<wmma::matrix_b,16,16,16,__half,wmma::row_major> FragBh;
typedef wmma::fragment<wmma::accumulator,16,16,16,float> FragCh;

template<class F> __device__ __forceinline__ void cvt_tf32(F& f){
    #pragma unroll
    for(int i=0;i<f.num_elements;i++) f.x[i]=wmma::__float_to_tf32(f.x[i]);
}

// =======================================================================
// K1: QKV projection (tf32 TC).
// =======================================================================
__global__ void __launch_bounds__(256) proj_tc(const float* __restrict__ X,
    const float* __restrict__ W, const float* __restrict__ bias, int sel)
{
    __shared__ float sx[128*72];
    int tid=threadIdx.x, w=tid>>5;
    int m0=blockIdx.x*128, o0=blockIdx.y*64;
    int wy=w&3, wx=w>>2;
    FragC acc[2][2];
    #pragma unroll
    for(int r=0;r<2;r++)
        #pragma unroll
        for(int c=0;c<2;c++) wmma::fill_fragment(acc[r][c],0.f);

    for(int k0=0;k0<Edim;k0+=8){
        FragA a[2]; FragBc b[2];
        #pragma unroll
        for(int r=0;r<2;r++){
            wmma::load_matrix_sync(a[r], X+(size_t)(m0+wy*32+r*16)*Edim+k0, Edim);
            cvt_tf32(a[r]);
        }
        #pragma unroll
        for(int c=0;c<2;c++){
            wmma::load_matrix_sync(b[c], W+(size_t)(o0+wx*32+c*16)*Edim+k0, Edim);
            cvt_tf32(b[c]);
        }
        #pragma unroll
        for(int r=0;r<2;r++)
            #pragma unroll
            for(int c=0;c<2;c++) wmma::mma_sync(acc[r][c],a[r],b[c],acc[r][c]);
    }
    #pragma unroll
    for(int r=0;r<2;r++)
        #pragma unroll
        for(int c=0;c<2;c++)
            wmma::store_matrix_sync(&sx[(wy*32+r*16)*72+wx*32+c*16],acc[r][c],72,wmma::mem_row_major);
    __syncthreads();

    float* out=(sel==0)?g_q:((sel==1)?g_k:g_v);
    int r=tid>>1, half=tid&1;
    int m=m0+r, s=m>>3, bb=m&7, h=blockIdx.y;
    size_t base=((size_t)(bb*Hdim+h)*Sdim+s)*Ddim + half*32;
    #pragma unroll
    for(int u=0;u<8;u++){
        int d=half*32+u*4;
        float4 v=*(float4*)&sx[r*72+d];
        v.x+=bias[o0+d]; v.y+=bias[o0+d+1]; v.z+=bias[o0+d+2]; v.w+=bias[o0+d+3];
        *(float4*)&out[base+u*4]=v;
    }
}

// =======================================================================
// K2: edge-key bias (tf32 TC) -> fp16.  per j: bias[j][i][n] = ek[j][i][:].q[n][j][:]
// smem-staged operands; i-tile 64.
// =======================================================================
__global__ void __launch_bounds__(256) biasgemm_tc(const float* __restrict__ ek)
{
    __shared__ float s_ek[64*72];   // [i][d], later reused for output
    __shared__ float s_q[64*72];    // [n][d]
    int tid=threadIdx.x, w=tid>>5;
    int i0=blockIdx.x*64; int j=blockIdx.y;

    const float* ekp = ek + (size_t)j*(Sdim*Ddim) + (size_t)i0*Ddim;  // contiguous 16KB
    for(int idx=tid; idx<1024; idx+=256){
        int r=idx>>4, c=(idx&15)*4;
        *(float4*)&s_ek[r*72+c] = *(const float4*)&ekp[r*64+c];
        *(float4*)&s_q[r*72+c]  = *(const float4*)&g_q[(size_t)r*(Sdim*Ddim)+(size_t)j*Ddim+c];
    }
    __syncthreads();

    int wy=w&3, wx=w>>2;  // i strip 16, n half 32
    FragC acc[2];
    wmma::fill_fragment(acc[0],0.f); wmma::fill_fragment(acc[1],0.f);
    #pragma unroll
    for(int kk=0;kk<8;kk++){
        FragA a; wmma::load_matrix_sync(a, &s_ek[(wy*16)*72+kk*8], 72); cvt_tf32(a);
        #pragma unroll
        for(int c=0;c<2;c++){
            FragBc b; wmma::load_matrix_sync(b, &s_q[(wx*32+c*16)*72+kk*8], 72); cvt_tf32(b);
            wmma::mma_sync(acc[c],a,b,acc[c]);
        }
    }
    __syncthreads();
    #pragma unroll
    for(int c=0;c<2;c++)
        wmma::store_matrix_sync(&s_ek[(wy*16)*72 + wx*32 + c*16], acc[c], 72, wmma::mem_row_major);
    __syncthreads();

    for(int idx=tid; idx<2048; idx+=256){   // 64 i x 32 half2
        int r=idx>>5, c2=(idx&31)*2;
        __half2 h = __floats2half2_rn(s_ek[r*72+c2], s_ek[r*72+c2+1]);
        *(__half2*)&g_bias_h[(size_t)j*(Sdim*Ndim)+(size_t)(i0+r)*Ndim + c2] = h;
    }
}

// =======================================================================
// K3: scores + bias + mask + scale (tf32 TC) -> fp32 logits.
// grid.x = n (fastest) so 64 n-sibling blocks share bias lines via L2.
// =======================================================================
__global__ void __launch_bounds__(256) score_tc(const int* __restrict__ mask)
{
    __shared__ float s_q[64*72];    // later reused for logits
    __shared__ float s_k[64*72];
    int tid=threadIdx.x, w=tid>>5;
    int n=blockIdx.x, i0=blockIdx.y*64, j0=blockIdx.z*64;

    for(int idx=tid; idx<1024; idx+=256){
        int r=idx>>4, c=(idx&15)*4;
        *(float4*)&s_q[r*72+c] = *(const float4*)&g_q[(size_t)n*(Sdim*Ddim)+(size_t)(i0+r)*Ddim+c];
        *(float4*)&s_k[r*72+c] = *(const float4*)&g_k[(size_t)n*(Sdim*Ddim)+(size_t)(j0+r)*Ddim+c];
    }
    __syncthreads();

    int wy=w&3, wx=w>>2;  // i strip 16, j half 32
    FragC acc[2];
    wmma::fill_fragment(acc[0],0.f); wmma::fill_fragment(acc[1],0.f);
    #pragma unroll
    for(int kk=0;kk<8;kk++){
        FragA a; wmma::load_matrix_sync(a, &s_q[(wy*16)*72+kk*8], 72); cvt_tf32(a);
        #pragma unroll
        for(int c=0;c<2;c++){
            FragBc b; wmma::load_matrix_sync(b, &s_k[(wx*32+c*16)*72+kk*8], 72); cvt_tf32(b);
            wmma::mma_sync(acc[c],a,b,acc[c]);
        }
    }
    __syncthreads();
    #pragma unroll
    for(int c=0;c<2;c++)
        wmma::store_matrix_sync(&s_q[(wy*16)*72 + wx*32 + c*16], acc[c], 72, wmma::mem_row_major);
    __syncthreads();

    size_t mbase = (size_t)n*Sdim*Sdim;
    for(int idx=tid; idx<1024; idx+=256){
        int r=idx>>4, jj=(idx&15)*4;
        int gi=i0+r, gj=j0+jj;
        int4 mv = *(const int4*)&mask[mbase + (size_t)gi*Sdim + gj];
        float b0=__half2float(g_bias_h[(size_t)(gj+0)*(Sdim*Ndim)+(size_t)gi*Ndim+n]);
        float b1=__half2float(g_bias_h[(size_t)(gj+1)*(Sdim*Ndim)+(size_t)gi*Ndim+n]);
        float b2=__half2float(g_bias_h[(size_t)(gj+2)*(Sdim*Ndim)+(size_t)gi*Ndim+n]);
        float b3=__half2float(g_bias_h[(size_t)(gj+3)*(Sdim*Ndim)+(size_t)gi*Ndim+n]);
        float4 qk=*(float4*)&s_q[r*72+jj];
        float4 o;
        o.x = mv.x ? -1e30f : (qk.x+b0)*0.125f;
        o.y = mv.y ? -1e30f : (qk.y+b1)*0.125f;
        o.z = mv.z ? -1e30f : (qk.z+b2)*0.125f;
        o.w = mv.w ? -1e30f : (qk.w+b3)*0.125f;
        *(float4*)&g_attn[mbase + (size_t)gi*Sdim + gj] = o;
    }
}

// =======================================================================
// K4: streaming softmax: fp32 logits -> fp16 probs. 1 warp per row.
// =======================================================================
__global__ void __launch_bounds__(256) softmax_k()
{
    int w=threadIdx.x>>5, lane=threadIdx.x&31;
    size_t row=(size_t)blockIdx.x*8 + w;
    const float* src = g_attn + row*Sdim;
    __half* dst = g_attn_h + row*Sdim;
    float x[32];
    float mx=-1e30f;
    #pragma unroll
    for(int t=0;t<8;t++){
        float4 v=*(const float4*)&src[(t*32+lane)*4];
        x[t*4]=v.x; x[t*4+1]=v.y; x[t*4+2]=v.z; x[t*4+3]=v.w;
        mx=fmaxf(mx,fmaxf(fmaxf(v.x,v.y),fmaxf(v.z,v.w)));
    }
    #pragma unroll
    for(int o=16;o;o>>=1) mx=fmaxf(mx,__shfl_xor_sync(0xffffffffu,mx,o));
    float sm=0.f;
    #pragma unroll
    for(int t=0;t<32;t++){ x[t]=__expf(x[t]-mx); sm+=x[t]; }
    #pragma unroll
    for(int o=16;o;o>>=1) sm+=__shfl_xor_sync(0xffffffffu,sm,o);
    float inv=1.0f/sm;
    #pragma unroll
    for(int t=0;t<8;t++){
        int j=(t*32+lane)*4;
        *(__half2*)&dst[j]   = __floats2half2_rn(x[t*4]*inv,   x[t*4+1]*inv);
        *(__half2*)&dst[j+2] = __floats2half2_rn(x[t*4+2]*inv, x[t*4+3]*inv);
    }
}

// =======================================================================
// K5a: PV (fp16 TC).  ctx[i][n*64+d] = sum_j p[n,i,j]*v[n,j,d]
// =======================================================================
__global__ void __launch_bounds__(256) pv_tc()
{
    __shared__ __half ps[128*80];   // [i][j]
    __shared__ __half vs[64*80];    // [j][d]
    int tid=threadIdx.x, w=tid>>5;
    int i0=blockIdx.x*128, n=blockIdx.y;
    FragCh acc[4];
    #pragma unroll
    for(int c=0;c<4;c++) wmma::fill_fragment(acc[c],0.f);

    for(int j0=0;j0<Sdim;j0+=64){
        for(int idx=tid; idx<1024; idx+=256){
            int r=idx>>3, u=(idx&7)*8;
            *(uint4*)&ps[r*80+u] =
                *(const uint4*)&g_attn_h[((size_t)n<<20)+(size_t)(i0+r)*Sdim + j0 + u];
        }
        for(int idx=tid; idx<1024; idx+=256){
            int r=idx>>4, c=(idx&15)*4;
            float4 v=*(const float4*)&g_v[(size_t)n*(Sdim*Ddim)+(size_t)(j0+r)*Ddim+c];
            *(__half2*)&vs[r*80+c]   = __floats2half2_rn(v.x,v.y);
            *(__half2*)&vs[r*80+c+2] = __floats2half2_rn(v.z,v.w);
        }
        __syncthreads();
        #pragma unroll
        for(int kk=0;kk<4;kk++){
            FragAh a; wmma::load_matrix_sync(a, &ps[(w*16)*80 + kk*16], 80);
            #pragma unroll
            for(int c=0;c<4;c++){
                FragBh b; wmma::load_matrix_sync(b, &vs[(kk*16)*80 + c*16], 80);
                wmma::mma_sync(acc[c],a,b,acc[c]);
            }
        }
        __syncthreads();
    }
    #pragma unroll
    for(int c=0;c<4;c++)
        wmma::store_matrix_sync(&g_ctx[(size_t)(i0+w*16)*(Bdim*Edim)+(size_t)n*Ddim+c*16],
                                acc[c], Bdim*Edim, wmma::mem_row_major);
}

// =======================================================================
// K5b: edge-value (fp16 TC).  per i: ctx[i][n*64+d] += p[:,i,:] @ ev[i]
// =======================================================================
__global__ void __launch_bounds__(256) ev_tc(const float* __restrict__ ev)
{
    __shared__ __half ps[64*80];    // [n][j]
    __shared__ __half es[64*80];    // [j][d]
    int tid=threadIdx.x, w=tid>>5;
    int wn=w&3, wd=w>>2;
    int i=blockIdx.x;
    FragCh acc[2];
    #pragma unroll
    for(int c=0;c<2;c++)
        wmma::load_matrix_sync(acc[c],
            &g_ctx[(size_t)i*(Bdim*Edim)+(size_t)(wn*16)*Ddim + wd*32 + c*16],
            Ddim, wmma::mem_row_major);

    for(int j0=0;j0<Sdim;j0+=64){
        for(int idx=tid; idx<512; idx+=256){
            int r=idx>>3, u=(idx&7)*8;
            *(uint4*)&ps[r*80+u] =
                *(const uint4*)&g_attn_h[((size_t)r<<20)+(size_t)i*Sdim + j0 + u];
        }
        for(int idx=tid; idx<1024; idx+=256){
            int r=idx>>4, c=(idx&15)*4;
            float4 v=*(const float4*)&ev[(size_t)i*(Sdim*Ddim)+(size_t)(j0+r)*Ddim+c];
            *(__half2*)&es[r*80+c]   = __floats2half2_rn(v.x,v.y);
            *(__half2*)&es[r*80+c+2] = __floats2half2_rn(v.z,v.w);
        }
        __syncthreads();
        #pragma unroll
        for(int kk=0;kk<4;kk++){
            FragAh a; wmma::load_matrix_sync(a, &ps[(wn*16)*80 + kk*16], 80);
            #pragma unroll
            for(int c=0;c<2;c++){
                FragBh b; wmma::load_matrix_sync(b, &es[(kk*16)*80 + wd*32 + c*16], 80);
                wmma::mma_sync(acc[c],a,b,acc[c]);
            }
        }
        __syncthreads();
    }
    #pragma unroll
    for(int c=0;c<2;c++)
        wmma::store_matrix_sync(&g_ctx[(size_t)i*(Bdim*Edim)+(size_t)(wn*16)*Ddim + wd*32 + c*16],
                                acc[c], Ddim, wmma::mem_row_major);
}

// =======================================================================
// K6: output projection + residual (tf32 TC) -> g_x
// =======================================================================
__global__ void __launch_bounds__(256) outproj_tc(const float* __restrict__ W,
    const float* __restrict__ bias, const float* __restrict__ resid)
{
    __shared__ float sx[128*72];
    int tid=threadIdx.x, w=tid>>5;
    int m0=blockIdx.x*128, o0=blockIdx.y*64;
    int wy=w&3, wx=w>>2;
    FragC acc[2][2];
    #pragma unroll
    for(int r=0;r<2;r++)
        #pragma unroll
        for(int c=0;c<2;c++) wmma::fill_fragment(acc[r][c],0.f);

    for(int k0=0;k0<Edim;k0+=8){
        FragA a[2]; FragBc b[2];
        #pragma unroll
        for(int r=0;r<2;r++){
            wmma::load_matrix_sync(a[r], g_ctx+(size_t)(m0+wy*32+r*16)*Edim+k0, Edim);
            cvt_tf32(a[r]);
        }
        #pragma unroll
        for(int c=0;c<2;c++){
            wmma::load_matrix_sync(b[c], W+(size_t)(o0+wx*32+c*16)*Edim+k0, Edim);
            cvt_tf32(b[c]);
        }
        #pragma unroll
        for(int r=0;r<2;r++)
            #pragma unroll
            for(int c=0;c<2;c++) wmma::mma_sync(acc[r][c],a[r],b[c],acc[r][c]);
    }
    #pragma unroll
    for(int r=0;r<2;r++)
        #pragma unroll
        for(int c=0;c<2;c++)
            wmma::store_matrix_sync(&sx[(wy*32+r*16)*72+wx*32+c*16],acc[r][c],72,wmma::mem_row_major);
    __syncthreads();

    int r=tid>>1, half=tid&1;
    int m=m0+r;
    size_t base=(size_t)m*Edim + o0 + half*32;
    #pragma unroll
    for(int u=0;u<8;u++){
        int d=half*32+u*4;
        float4 v=*(float4*)&sx[r*72+d];
        float4 rs=*(const float4*)&resid[base+u*4];
        v.x+=bias[o0+d]  +rs.x; v.y+=bias[o0+d+1]+rs.y;
        v.z+=bias[o0+d+2]+rs.z; v.w+=bias[o0+d+3]+rs.w;
        *(float4*)&g_x[base+u*4]=v;
    }
}

// =======================================================================
// K7: LayerNorm over last dim (512)
// =======================================================================
__global__ void __launch_bounds__(256) ln_kernel(const float* __restrict__ gamma,
     const float* __restrict__ beta, float* __restrict__ out)
{
    int m = blockIdx.x, tid = threadIdx.x;
    float a = g_x[(size_t)m*Edim + tid];
    float b = g_x[(size_t)m*Edim + 256 + tid];
    __shared__ float s1[256], s2[256];
    s1[tid] = a+b; s2[tid] = a*a + b*b;
    __syncthreads();
    for (int s=128;s>0;s>>=1){
        if(tid<s){ s1[tid]+=s1[tid+s]; s2[tid]+=s2[tid+s]; }
        __syncthreads();
    }
    float mean = s1[0] * (1.0f/512.0f);
    float var  = s2[0] * (1.0f/512.0f) - mean*mean;
    float rstd = rsqrtf(var + 1e-5f);
    out[(size_t)m*Edim + tid]       = gamma[tid]*(a-mean)*rstd + beta[tid];
    out[(size_t)m*Edim + 256 + tid] = gamma[256+tid]*(b-mean)*rstd + beta[256+tid];
}

// =======================================================================
extern "C" void kernel_launch(void* const* d_in, const int* in_sizes, int n_in,
                              void* d_out, int out_size)
{
    const float* query      = (const float*)d_in[0];
    const float* key        = (const float*)d_in[1];
    const float* value      = (const float*)d_in[2];
    const float* edge_key   = (const float*)d_in[3];
    const float* edge_value = (const float*)d_in[4];
    const int*   mask       = (const int*)  d_in[5];
    int base = (n_in == 17) ? 7 : 6;
    const float* Wq = (const float*)d_in[base+0];
    const float* bq = (const float*)d_in[base+1];
    const float* Wk = (const float*)d_in[base+2];
    const float* bk = (const float*)d_in[base+3];
    const float* Wv = (const float*)d_in[base+4];
    const float* bv = (const float*)d_in[base+5];
    const float* Wo = (const float*)d_in[base+6];
    const float* bo = (const float*)d_in[base+7];
    const float* gamma = (const float*)d_in[base+8];
    const float* beta  = (const float*)d_in[base+9];

    proj_tc<<<dim3(64,8),256>>>(query, Wq, bq, 0);
    proj_tc<<<dim3(64,8),256>>>(key,   Wk, bk, 1);
    proj_tc<<<dim3(64,8),256>>>(value, Wv, bv, 2);
    biasgemm_tc<<<dim3(16,1024),256>>>(edge_key);
    score_tc<<<dim3(64,16,16),256>>>(mask);          // x=n fastest for bias L2 sharing
    softmax_k<<<8192,256>>>();
    pv_tc<<<dim3(8,64),256>>>();
    ev_tc<<<1024,256>>>(edge_value);
    outproj_tc<<<dim3(64,8),256>>>(Wo, bo, query);
    ln_kernel<<<dim3(8192),256>>>(gamma, beta, (float*)d_out);
}